// round 12
// baseline (speedup 1.0000x reference)
#include <cuda_runtime.h>
#include <cstdint>
#include <cstddef>

// ---------------- problem constants ----------------
#define BATCH   16
#define CIN     256
#define COUT    256
#define HW      64
#define KBANK   4
#define HIDDEN  65
#define TEMP    34.0f
#define BANK_K_STRIDE (256*256*9)
#define BANK_O_STRIDE (256*9)

// ---------------- conv tiling ----------------
// CTA: 128 oc x 256 px (4 output rows). 8 warps = 2(M) x 4(N), warp tile 64x64.
// K = 2304 processed as 8 ci-chunks of 32 x 9 kernel shifts.
#define ASTR  36                 // A smem row stride (floats); 36 % 32 == 4 -> conflict-free frags
#define XRCI  424                // x-row cache ci stride (floats); 424 % 32 == 8 -> conflict-free
#define SM_A_BYTES  (128 * ASTR * 4)        // 18432
#define SM_XR_OFF   SM_A_BYTES
#define SM_TOTAL    (SM_XR_OFF + 32 * XRCI * 4)   // 18432 + 54272 = 72704

// ---------------- scratch (allocation-free) ----------------
__device__ float g_pooled[BATCH * CIN];
__device__ float g_att[BATCH * KBANK];
__device__ float g_aggw[BATCH * 9 * COUT * CIN];   // [b][rs][oc][ci], tf32-rounded

// ---------------- helpers ----------------
__device__ __forceinline__ uint32_t f2tf32(float f) {
    uint32_t u;
    asm("cvt.rna.tf32.f32 %0, %1;" : "=r"(u) : "f"(f));
    return u;
}

__device__ __forceinline__ void mma_tf32(float* d, const uint32_t* a, const uint32_t* b) {
    asm volatile(
        "mma.sync.aligned.m16n8k8.row.col.f32.tf32.tf32.f32 "
        "{%0,%1,%2,%3}, {%4,%5,%6,%7}, {%8,%9}, {%0,%1,%2,%3};"
        : "+f"(d[0]), "+f"(d[1]), "+f"(d[2]), "+f"(d[3])
        : "r"(a[0]), "r"(a[1]), "r"(a[2]), "r"(a[3]), "r"(b[0]), "r"(b[1]));
}

// ---------------- Kernel 1: global average pool ----------------
__global__ void pool_kernel(const float* __restrict__ x) {
    const int bc = blockIdx.x;
    const float4* p = (const float4*)(x + (size_t)bc * (HW * HW));
    float s = 0.f;
#pragma unroll 4
    for (int i = threadIdx.x; i < 1024; i += 256) {
        float4 v = p[i];
        s += (v.x + v.y) + (v.z + v.w);
    }
#pragma unroll
    for (int o = 16; o > 0; o >>= 1) s += __shfl_xor_sync(0xFFFFFFFFu, s, o);
    __shared__ float red[8];
    if ((threadIdx.x & 31) == 0) red[threadIdx.x >> 5] = s;
    __syncthreads();
    if (threadIdx.x == 0) {
        float t = 0.f;
#pragma unroll
        for (int w = 0; w < 8; w++) t += red[w];
        g_pooled[bc] = t * (1.0f / (HW * HW));
    }
}

// ---------------- Kernel 2: attention MLP + softmax ----------------
__global__ void att_kernel(const float* __restrict__ w1,
                           const float* __restrict__ w2,
                           const float* __restrict__ b2) {
    const int b = blockIdx.x;
    const int j = threadIdx.x;
    __shared__ float hs[HIDDEN];
    if (j < HIDDEN) {
        const float* pr = &g_pooled[b * CIN];
        const float* wr = &w1[j * CIN];
        float s = 0.f;
#pragma unroll 4
        for (int c = 0; c < CIN; c++) s += pr[c] * wr[c];
        hs[j] = fmaxf(s, 0.f);
    }
    __syncthreads();
    if (j == 0) {
        float lg[KBANK];
#pragma unroll
        for (int k = 0; k < KBANK; k++) {
            float s = b2[k];
            for (int h = 0; h < HIDDEN; h++) s += hs[h] * w2[k * HIDDEN + h];
            lg[k] = s * (1.0f / TEMP);
        }
        float m = lg[0];
#pragma unroll
        for (int k = 1; k < KBANK; k++) m = fmaxf(m, lg[k]);
        float e[KBANK], Z = 0.f;
#pragma unroll
        for (int k = 0; k < KBANK; k++) { e[k] = expf(lg[k] - m); Z += e[k]; }
        float inv = 1.0f / Z;
#pragma unroll
        for (int k = 0; k < KBANK; k++) g_att[b * KBANK + k] = e[k] * inv;
    }
}

// ---------------- Kernel 3: weight aggregation -> [b][rs][oc][ci], tf32-rounded ---
__global__ void agg_kernel(const float* __restrict__ bank) {
    const int oc = blockIdx.x;
    const int b  = blockIdx.y;
    const float a0 = g_att[b * 4 + 0], a1 = g_att[b * 4 + 1];
    const float a2 = g_att[b * 4 + 2], a3 = g_att[b * 4 + 3];
    const float* w = bank + (size_t)oc * BANK_O_STRIDE;
    uint32_t* dst = (uint32_t*)g_aggw + (size_t)b * 9 * 65536 + oc * 256;
    for (int t = threadIdx.x; t < 2304; t += 256) {
        float v = a0 * w[t] + a1 * w[t + BANK_K_STRIDE]
                + a2 * w[t + 2 * BANK_K_STRIDE] + a3 * w[t + 3 * BANK_K_STRIDE];
        int ci = t / 9;
        int rs = t - 9 * ci;
        dst[rs * 65536 + ci] = f2tf32(v);
    }
}

// ---------------- Kernel 4: tf32 mma.sync implicit-GEMM conv ----------------
__global__ __launch_bounds__(256, 1)
void conv_mma(const float* __restrict__ x, float* __restrict__ out) {
    extern __shared__ char smem[];
    float*    A_f  = (float*)smem;                  // [128][ASTR]
    uint32_t* A_u  = (uint32_t*)smem;
    uint32_t* xr   = (uint32_t*)(smem + SM_XR_OFF); // [32 ci][6 rows][68] stride XRCI

    const int tid  = threadIdx.x;
    const int wid  = tid >> 5;
    const int lane = tid & 31;
    const int g    = lane >> 2;      // group id (0..7)
    const int t    = lane & 3;       // thread in group (0..3)
    const int wm   = wid & 1;        // warp M tile (0..1)
    const int wn   = wid >> 1;       // warp N tile (0..3) == output row within CTA

    const int b   = blockIdx.z;
    const int oc0 = blockIdx.y << 7;
    const int y0  = blockIdx.x << 2; // 4 output rows per CTA

    const float* xb = x + (size_t)b * (CIN * HW * HW);
    const float* wb = g_aggw + (size_t)b * 9 * 65536;

    float acc[4][8][4];
#pragma unroll
    for (int mf = 0; mf < 4; mf++)
#pragma unroll
        for (int nf = 0; nf < 8; nf++)
#pragma unroll
            for (int k = 0; k < 4; k++) acc[mf][nf][k] = 0.f;

    // per-thread invariant bases
    const uint32_t* a_base = A_u + (wm * 64 + g) * ASTR + t;
    const uint32_t* x_base = xr + t * XRCI + wn * 68 + g;

    for (int chunk = 0; chunk < 8; chunk++) {
        const int ci0 = chunk * 32;
        __syncthreads();   // previous compute done reading xr
        // ---- stage x rows: 32 ci x 6 rows x cols -1..64 (tf32 rounded, zero halo) ----
        for (int q = tid; q < 32 * 6 * 16; q += 256) {
            int ci  = q / 96;
            int rem = q - ci * 96;
            int ri  = rem >> 4;
            int c4  = (rem & 15) << 2;
            int xrow = y0 - 1 + ri;
            float4 v = make_float4(0.f, 0.f, 0.f, 0.f);
            if ((unsigned)xrow < (unsigned)HW)
                v = *(const float4*)(xb + (size_t)(ci0 + ci) * (HW * HW) + xrow * HW + c4);
            uint32_t* d = xr + ci * XRCI + ri * 68 + 1 + c4;
            d[0] = f2tf32(v.x); d[1] = f2tf32(v.y); d[2] = f2tf32(v.z); d[3] = f2tf32(v.w);
        }
        if (tid < 192) {    // zero halo columns
            int ci = tid / 6, ri = tid - 6 * ci;
            uint32_t* d = xr + ci * XRCI + ri * 68;
            d[0] = 0u; d[65] = 0u;
        }

        for (int rs = 0; rs < 9; rs++) {
            __syncthreads();   // xr staged / previous A consumed
            // ---- stage A: 128 oc x 32 ci for this (rs, chunk) ----
            const float* arow = wb + (size_t)rs * 65536 + oc0 * 256 + ci0;
#pragma unroll
            for (int i = 0; i < 4; i++) {
                int q  = tid + i * 256;
                int m  = q >> 3;
                int kq = (q & 7) << 2;
                float4 v = *(const float4*)(arow + m * 256 + kq);
                float* dA = A_f + m * ASTR + kq;
                *(float2*)(dA)     = make_float2(v.x, v.y);
                *(float2*)(dA + 2) = make_float2(v.z, v.w);
            }
            __syncthreads();

            const int r = rs / 3, s = rs - 3 * r;
            const uint32_t* xs_ = x_base + r * 68 + s;
#pragma unroll
            for (int ks = 0; ks < 4; ks++) {
                const uint32_t* ap = a_base + ks * 8;
                uint32_t af[4][4];
#pragma unroll
                for (int mf = 0; mf < 4; mf++) {
                    const uint32_t* am = ap + mf * 16 * ASTR;
                    af[mf][0] = am[0];
                    af[mf][1] = am[8 * ASTR];
                    af[mf][2] = am[4];
                    af[mf][3] = am[8 * ASTR + 4];
                }
                const uint32_t* xp = xs_ + ks * 8 * XRCI;
                uint32_t bf[8][2];
#pragma unroll
                for (int nf = 0; nf < 8; nf++) {
                    bf[nf][0] = xp[nf * 8];
                    bf[nf][1] = xp[nf * 8 + 4 * XRCI];
                }
#pragma unroll
                for (int mf = 0; mf < 4; mf++)
#pragma unroll
                    for (int nf = 0; nf < 8; nf++)
                        mma_tf32(acc[mf][nf], af[mf], bf[nf]);
            }
        }
    }

    // ---- epilogue: D[m=16x8 frag] -> out[b][oc][y0+wn][px] ----
    const int ocr = oc0 + wm * 64 + g;
    const int yrow = (y0 + wn) * 64;
#pragma unroll
    for (int mf = 0; mf < 4; mf++) {
        float* o0 = out + ((size_t)(b * COUT + ocr + mf * 16)) * (HW * HW) + yrow;
        float* o1 = o0 + 8 * (HW * HW);
#pragma unroll
        for (int nf = 0; nf < 8; nf++) {
            int px0 = nf * 8 + 2 * t;
            *(float2*)(o0 + px0) = make_float2(acc[mf][nf][0], acc[mf][nf][1]);
            *(float2*)(o1 + px0) = make_float2(acc[mf][nf][2], acc[mf][nf][3]);
        }
    }
}

// ---------------- launch ----------------
extern "C" void kernel_launch(void* const* d_in, const int* in_sizes, int n_in,
                              void* d_out, int out_size) {
    (void)in_sizes; (void)n_in; (void)out_size;
    const float* x    = (const float*)d_in[0];  // [16,256,64,64]
    const float* bank = (const float*)d_in[1];  // [4,256,256,3,3]
    const float* w1   = (const float*)d_in[2];  // [65,256]
    const float* w2   = (const float*)d_in[3];  // [4,65]
    const float* b2   = (const float*)d_in[4];  // [4]
    float* out = (float*)d_out;                 // [16,256,64,64]

    static bool attr_set = false;
    if (!attr_set) {
        cudaFuncSetAttribute(conv_mma, cudaFuncAttributeMaxDynamicSharedMemorySize, SM_TOTAL);
        attr_set = true;
    }

    pool_kernel<<<BATCH * CIN, 256>>>(x);
    att_kernel<<<BATCH, 128>>>(w1, w2, b2);
    agg_kernel<<<dim3(COUT, BATCH), 256>>>(bank);
    conv_mma<<<dim3(16, 2, BATCH), 256, SM_TOTAL>>>(x, out);
}

// round 13
// speedup vs baseline: 1.3593x; 1.3593x over previous
#include <cuda_runtime.h>
#include <cstdint>
#include <cstddef>

// ---------------- problem constants ----------------
#define BATCH   16
#define CIN     256
#define COUT    256
#define HW      64
#define KBANK   4
#define HIDDEN  65
#define TEMP    34.0f
#define BANK_K_STRIDE (256*256*9)
#define BANK_O_STRIDE (256*9)

// ---------------- conv tiling ----------------
// CTA: 128 oc x 256 px (4 output rows). 8 warps = 2(M) x 4(N), warp tile 64x64.
// K = 2304 as 8 ci-chunks of 32 x 9 kernel shifts = 72 stages, fully cp.async pipelined.
#define ASTR    36               // A smem row stride (floats); 36 % 32 == 4 -> conflict-free frags
#define A_HALF  (128 * ASTR)     // floats per A buffer (4608)
#define XRROW   72               // x-row cache row stride (floats); col c at offset 4+c, halos at 3 & 68
#define XRCI    456              // ci stride (floats); 456 % 32 == 8 -> conflict-free; mult of 4 -> 16B dst
#define XR_HALF (32 * XRCI)      // floats per xr buffer (14592)
#define SM_XR_OFF  (2 * A_HALF * 4)                 // 36864
#define SM_TOTAL   (SM_XR_OFF + 2 * XR_HALF * 4)    // 36864 + 116736 = 153600

// ---------------- scratch (allocation-free) ----------------
__device__ float    g_pooled[BATCH * CIN];
__device__ float    g_att[BATCH * KBANK];
__device__ float    g_aggw[BATCH * 9 * COUT * CIN];      // [b][rs][oc][ci], tf32-rounded
__device__ uint32_t g_xtf[BATCH * CIN * HW * HW];        // x, tf32-rounded bits

// ---------------- helpers ----------------
__device__ __forceinline__ uint32_t f2tf32(float f) {
    uint32_t u;
    asm("cvt.rna.tf32.f32 %0, %1;" : "=r"(u) : "f"(f));
    return u;
}
__device__ __forceinline__ uint32_t smem_u32(const void* p) {
    uint32_t a;
    asm("{ .reg .u64 t; cvta.to.shared.u64 t, %1; cvt.u32.u64 %0, t; }" : "=r"(a) : "l"(p));
    return a;
}
__device__ __forceinline__ void cp_async16(uint32_t dst, const void* src, uint32_t srcsize) {
    asm volatile("cp.async.cg.shared.global [%0], [%1], 16, %2;"
                 :: "r"(dst), "l"(src), "r"(srcsize) : "memory");
}
#define CP_COMMIT() asm volatile("cp.async.commit_group;" ::: "memory")
#define CP_WAIT0()  asm volatile("cp.async.wait_group 0;" ::: "memory")

__device__ __forceinline__ void mma_tf32(float* d, const uint32_t* a, const uint32_t* b) {
    asm volatile(
        "mma.sync.aligned.m16n8k8.row.col.f32.tf32.tf32.f32 "
        "{%0,%1,%2,%3}, {%4,%5,%6,%7}, {%8,%9}, {%0,%1,%2,%3};"
        : "+f"(d[0]), "+f"(d[1]), "+f"(d[2]), "+f"(d[3])
        : "r"(a[0]), "r"(a[1]), "r"(a[2]), "r"(a[3]), "r"(b[0]), "r"(b[1]));
}

// ---------------- Kernel 1: global average pool + x tf32 pre-round ----------------
__global__ void pool_kernel(const float* __restrict__ x) {
    const int bc = blockIdx.x;
    const float4* p = (const float4*)(x + (size_t)bc * (HW * HW));
    uint4* q = (uint4*)(g_xtf + (size_t)bc * (HW * HW));
    float s = 0.f;
#pragma unroll 4
    for (int i = threadIdx.x; i < 1024; i += 256) {
        float4 v = p[i];
        s += (v.x + v.y) + (v.z + v.w);
        q[i] = make_uint4(f2tf32(v.x), f2tf32(v.y), f2tf32(v.z), f2tf32(v.w));
    }
#pragma unroll
    for (int o = 16; o > 0; o >>= 1) s += __shfl_xor_sync(0xFFFFFFFFu, s, o);
    __shared__ float red[8];
    if ((threadIdx.x & 31) == 0) red[threadIdx.x >> 5] = s;
    __syncthreads();
    if (threadIdx.x == 0) {
        float t = 0.f;
#pragma unroll
        for (int w = 0; w < 8; w++) t += red[w];
        g_pooled[bc] = t * (1.0f / (HW * HW));
    }
}

// ---------------- Kernel 2: attention MLP + softmax ----------------
__global__ void att_kernel(const float* __restrict__ w1,
                           const float* __restrict__ w2,
                           const float* __restrict__ b2) {
    const int b = blockIdx.x;
    const int j = threadIdx.x;
    __shared__ float hs[HIDDEN];
    if (j < HIDDEN) {
        const float* pr = &g_pooled[b * CIN];
        const float* wr = &w1[j * CIN];
        float s = 0.f;
#pragma unroll 4
        for (int c = 0; c < CIN; c++) s += pr[c] * wr[c];
        hs[j] = fmaxf(s, 0.f);
    }
    __syncthreads();
    if (j == 0) {
        float lg[KBANK];
#pragma unroll
        for (int k = 0; k < KBANK; k++) {
            float s = b2[k];
            for (int h = 0; h < HIDDEN; h++) s += hs[h] * w2[k * HIDDEN + h];
            lg[k] = s * (1.0f / TEMP);
        }
        float m = lg[0];
#pragma unroll
        for (int k = 1; k < KBANK; k++) m = fmaxf(m, lg[k]);
        float e[KBANK], Z = 0.f;
#pragma unroll
        for (int k = 0; k < KBANK; k++) { e[k] = expf(lg[k] - m); Z += e[k]; }
        float inv = 1.0f / Z;
#pragma unroll
        for (int k = 0; k < KBANK; k++) g_att[b * KBANK + k] = e[k] * inv;
    }
}

// ---------------- Kernel 3: weight aggregation -> [b][rs][oc][ci], tf32-rounded ---
__global__ void agg_kernel(const float* __restrict__ bank) {
    const int oc = blockIdx.x;
    const int b  = blockIdx.y;
    const float a0 = g_att[b * 4 + 0], a1 = g_att[b * 4 + 1];
    const float a2 = g_att[b * 4 + 2], a3 = g_att[b * 4 + 3];
    const float* w = bank + (size_t)oc * BANK_O_STRIDE;
    uint32_t* dst = (uint32_t*)g_aggw + (size_t)b * 9 * 65536 + oc * 256;
    for (int t = threadIdx.x; t < 2304; t += 256) {
        float v = a0 * w[t] + a1 * w[t + BANK_K_STRIDE]
                + a2 * w[t + 2 * BANK_K_STRIDE] + a3 * w[t + 3 * BANK_K_STRIDE];
        int ci = t / 9;
        int rs = t - 9 * ci;
        dst[rs * 65536 + ci] = f2tf32(v);
    }
}

// ---------------- Kernel 4: tf32 mma.sync conv, cp.async double-buffered ----------
__global__ __launch_bounds__(256, 1)
void conv_mma(float* __restrict__ out) {
    extern __shared__ char smem[];
    uint32_t* A_u = (uint32_t*)smem;                     // 2 x [128][ASTR]
    uint32_t* xr  = (uint32_t*)(smem + SM_XR_OFF);       // 2 x [32 ci][6 rows][XRROW]
    const uint32_t A_sb  = smem_u32(smem);
    const uint32_t XR_sb = A_sb + SM_XR_OFF;

    const int tid  = threadIdx.x;
    const int wid  = tid >> 5;
    const int lane = tid & 31;
    const int g    = lane >> 2;
    const int t    = lane & 3;
    const int wm   = wid & 1;        // warp M tile
    const int wn   = wid >> 1;       // warp N tile == output row within CTA

    const int b   = blockIdx.z;
    const int oc0 = blockIdx.y << 7;
    const int y0  = blockIdx.x << 2;

    const uint32_t* xtb = g_xtf + (size_t)b * (CIN * HW * HW);
    const float*    wb  = g_aggw + (size_t)b * 9 * 65536;

    float acc[4][8][4];
#pragma unroll
    for (int mf = 0; mf < 4; mf++)
#pragma unroll
        for (int nf = 0; nf < 8; nf++)
#pragma unroll
            for (int k = 0; k < 4; k++) acc[mf][nf][k] = 0.f;

    // per-thread A staging slots (4 x 16B)
    const int am0 = tid >> 3;            // oc row for i=0 (rows 0..31); +32 per i
    const int akq = (tid & 7) << 2;      // ci quad
    // per-thread xr staging: 12 x 16B over [32ci][6ri][16 quads]
    // q = tid + i*256, i=0..11 ; ci = q/96, ri = (q%96)>>4, c4 = (q&15)<<2

    // prologue: zero halo columns of both xr buffers (never rewritten)
    for (int q = tid; q < 2 * 32 * 6; q += 256) {
        int buf = q >= 192;
        int rem = buf ? q - 192 : q;
        int ci = rem / 6, ri = rem - 6 * ci;
        uint32_t* d = xr + buf * XR_HALF + ci * XRCI + ri * XRROW;
        d[3] = 0u; d[68] = 0u;
    }

    // issue stage-0 A and chunk-0 xr
    {
        const float* arow = wb + oc0 * 256;   // rs=0, ci0=0
#pragma unroll
        for (int i = 0; i < 4; i++) {
            int m = am0 + i * 32;
            cp_async16(A_sb + (m * ASTR + akq) * 4, arow + m * 256 + akq, 16);
        }
#pragma unroll
        for (int i = 0; i < 12; i++) {
            int q = tid + i * 256;
            int ci = q / 96, rem = q - ci * 96;
            int ri = rem >> 4, c4 = (rem & 15) << 2;
            int xrow = y0 - 1 + ri;
            uint32_t ok = ((unsigned)xrow < (unsigned)HW) ? 16u : 0u;
            cp_async16(XR_sb + (ci * XRCI + ri * XRROW + 4 + c4) * 4,
                       xtb + ci * (HW * HW) + xrow * HW + c4, ok);
        }
        CP_COMMIT();
    }

    // compute-invariant bases
    const uint32_t* a_tb = A_u + (wm * 64 + g) * ASTR + t;
    const uint32_t* x_tb = xr + t * XRCI + wn * XRROW + 3 + g;

    int chunk = 0, rs = 0;
    for (int s = 0; s < 72; s++) {
        CP_WAIT0();
        __syncthreads();

        // ---- prefetch next stage (overlaps with this stage's MMAs) ----
        int rs_n = rs + 1, chunk_n = chunk;
        if (rs_n == 9) { rs_n = 0; chunk_n++; }
        if (s + 1 < 72) {
            const float* arow = wb + (size_t)rs_n * 65536 + oc0 * 256 + chunk_n * 32;
            uint32_t Ad = A_sb + ((s + 1) & 1) * (A_HALF * 4);
#pragma unroll
            for (int i = 0; i < 4; i++) {
                int m = am0 + i * 32;
                cp_async16(Ad + (m * ASTR + akq) * 4, arow + m * 256 + akq, 16);
            }
        }
        if (rs == 0 && chunk + 1 < 8) {
            const uint32_t* xcb = xtb + (chunk + 1) * 32 * (HW * HW);
            uint32_t Xd = XR_sb + ((chunk + 1) & 1) * (XR_HALF * 4);
#pragma unroll
            for (int i = 0; i < 12; i++) {
                int q = tid + i * 256;
                int ci = q / 96, rem = q - ci * 96;
                int ri = rem >> 4, c4 = (rem & 15) << 2;
                int xrow = y0 - 1 + ri;
                uint32_t ok = ((unsigned)xrow < (unsigned)HW) ? 16u : 0u;
                cp_async16(Xd + (ci * XRCI + ri * XRROW + 4 + c4) * 4,
                           xcb + ci * (HW * HW) + xrow * HW + c4, ok);
            }
        }
        CP_COMMIT();

        // ---- compute stage s ----
        const int r = rs / 3, sc = rs - 3 * r;
        const uint32_t* a_base = a_tb + (s & 1) * A_HALF;
        const uint32_t* xs_ = x_tb + (chunk & 1) * XR_HALF + r * XRROW + sc;
#pragma unroll
        for (int ks = 0; ks < 4; ks++) {
            const uint32_t* ap = a_base + ks * 8;
            uint32_t af[4][4];
#pragma unroll
            for (int mf = 0; mf < 4; mf++) {
                const uint32_t* am = ap + mf * 16 * ASTR;
                af[mf][0] = am[0];
                af[mf][1] = am[8 * ASTR];
                af[mf][2] = am[4];
                af[mf][3] = am[8 * ASTR + 4];
            }
            const uint32_t* xp = xs_ + ks * 8 * XRCI;
            uint32_t bf[8][2];
#pragma unroll
            for (int nf = 0; nf < 8; nf++) {
                bf[nf][0] = xp[nf * 8];
                bf[nf][1] = xp[nf * 8 + 4 * XRCI];
            }
#pragma unroll
            for (int mf = 0; mf < 4; mf++)
#pragma unroll
                for (int nf = 0; nf < 8; nf++)
                    mma_tf32(acc[mf][nf], af[mf], bf[nf]);
        }

        if (++rs == 9) { rs = 0; chunk++; }
    }

    // ---- epilogue ----
    const int ocr = oc0 + wm * 64 + g;
    const int yrow = (y0 + wn) * 64;
#pragma unroll
    for (int mf = 0; mf < 4; mf++) {
        float* o0 = out + ((size_t)(b * COUT + ocr + mf * 16)) * (HW * HW) + yrow;
        float* o1 = o0 + 8 * (HW * HW);
#pragma unroll
        for (int nf = 0; nf < 8; nf++) {
            int px0 = nf * 8 + 2 * t;
            *(float2*)(o0 + px0) = make_float2(acc[mf][nf][0], acc[mf][nf][1]);
            *(float2*)(o1 + px0) = make_float2(acc[mf][nf][2], acc[mf][nf][3]);
        }
    }
}

// ---------------- launch ----------------
extern "C" void kernel_launch(void* const* d_in, const int* in_sizes, int n_in,
                              void* d_out, int out_size) {
    (void)in_sizes; (void)n_in; (void)out_size;
    const float* x    = (const float*)d_in[0];  // [16,256,64,64]
    const float* bank = (const float*)d_in[1];  // [4,256,256,3,3]
    const float* w1   = (const float*)d_in[2];  // [65,256]
    const float* w2   = (const float*)d_in[3];  // [4,65]
    const float* b2   = (const float*)d_in[4];  // [4]
    float* out = (float*)d_out;                 // [16,256,64,64]

    static bool attr_set = false;
    if (!attr_set) {
        cudaFuncSetAttribute(conv_mma, cudaFuncAttributeMaxDynamicSharedMemorySize, SM_TOTAL);
        attr_set = true;
    }

    pool_kernel<<<BATCH * CIN, 256>>>(x);
    att_kernel<<<BATCH, 128>>>(w1, w2, b2);
    agg_kernel<<<dim3(COUT, BATCH), 256>>>(bank);
    conv_mma<<<dim3(16, 2, BATCH), 256, SM_TOTAL>>>(out);
}

// round 14
// speedup vs baseline: 1.4283x; 1.0508x over previous
#include <cuda_runtime.h>
#include <cstdint>
#include <cstddef>

// ---------------- problem constants ----------------
#define BATCH   16
#define CIN     256
#define COUT    256
#define HW      64
#define KBANK   4
#define HIDDEN  65
#define TEMP    34.0f
#define BANK_K_STRIDE (256*256*9)
#define BANK_O_STRIDE (256*9)

// ---------------- conv tiling ----------------
// CTA: 128 oc x 128 px (2 output rows), 8 warps = 2(M) x 4(N), warp tile 64x32.
// 2 CTAs / SM. K = 2304 as 8 ci-chunks of 32 x 9 shifts = 72 cp.async stages.
#define ASTR    36               // A smem row stride (floats); 36 % 32 == 4 -> conflict-free frags
#define A_HALF  (128 * ASTR)     // floats per A buffer (4608)
#define XRROW   72               // x-row cache row stride; col c at 4+c, halos at 3 & 68
#define XRCI    296              // ci stride (4 rows*72=288 +8 pad); 296 % 32 == 8 -> conflict-free
#define XR_HALF (32 * XRCI)      // floats per xr buffer (9472)
#define SM_XR_OFF  (2 * A_HALF * 4)                 // 36864
#define SM_TOTAL   (SM_XR_OFF + 2 * XR_HALF * 4)    // 36864 + 75776 = 112640 (2 CTAs/SM)

// ---------------- scratch (allocation-free) ----------------
__device__ float    g_pooled[BATCH * CIN];
__device__ float    g_att[BATCH * KBANK];
__device__ float    g_aggw[BATCH * 9 * COUT * CIN];      // [b][rs][oc][ci], tf32-rounded
__device__ uint32_t g_xtf[BATCH * CIN * HW * HW];        // x, tf32-rounded bits

// ---------------- helpers ----------------
__device__ __forceinline__ uint32_t f2tf32(float f) {
    uint32_t u;
    asm("cvt.rna.tf32.f32 %0, %1;" : "=r"(u) : "f"(f));
    return u;
}
__device__ __forceinline__ uint32_t smem_u32(const void* p) {
    uint32_t a;
    asm("{ .reg .u64 t; cvta.to.shared.u64 t, %1; cvt.u32.u64 %0, t; }" : "=r"(a) : "l"(p));
    return a;
}
__device__ __forceinline__ void cp_async16(uint32_t dst, const void* src, uint32_t srcsize) {
    asm volatile("cp.async.cg.shared.global [%0], [%1], 16, %2;"
                 :: "r"(dst), "l"(src), "r"(srcsize) : "memory");
}
#define CP_COMMIT() asm volatile("cp.async.commit_group;" ::: "memory")
#define CP_WAIT0()  asm volatile("cp.async.wait_group 0;" ::: "memory")

__device__ __forceinline__ void mma_tf32(float* d, const uint32_t* a, const uint32_t* b) {
    asm volatile(
        "mma.sync.aligned.m16n8k8.row.col.f32.tf32.tf32.f32 "
        "{%0,%1,%2,%3}, {%4,%5,%6,%7}, {%8,%9}, {%0,%1,%2,%3};"
        : "+f"(d[0]), "+f"(d[1]), "+f"(d[2]), "+f"(d[3])
        : "r"(a[0]), "r"(a[1]), "r"(a[2]), "r"(a[3]), "r"(b[0]), "r"(b[1]));
}

// ---------------- Kernel 1: global average pool + x tf32 pre-round ----------------
__global__ void pool_kernel(const float* __restrict__ x) {
    const int bc = blockIdx.x;
    const float4* p = (const float4*)(x + (size_t)bc * (HW * HW));
    uint4* q = (uint4*)(g_xtf + (size_t)bc * (HW * HW));
    float s = 0.f;
#pragma unroll 4
    for (int i = threadIdx.x; i < 1024; i += 256) {
        float4 v = p[i];
        s += (v.x + v.y) + (v.z + v.w);
        q[i] = make_uint4(f2tf32(v.x), f2tf32(v.y), f2tf32(v.z), f2tf32(v.w));
    }
#pragma unroll
    for (int o = 16; o > 0; o >>= 1) s += __shfl_xor_sync(0xFFFFFFFFu, s, o);
    __shared__ float red[8];
    if ((threadIdx.x & 31) == 0) red[threadIdx.x >> 5] = s;
    __syncthreads();
    if (threadIdx.x == 0) {
        float t = 0.f;
#pragma unroll
        for (int w = 0; w < 8; w++) t += red[w];
        g_pooled[bc] = t * (1.0f / (HW * HW));
    }
}

// ---------------- Kernel 2: attention MLP + softmax ----------------
__global__ void att_kernel(const float* __restrict__ w1,
                           const float* __restrict__ w2,
                           const float* __restrict__ b2) {
    const int b = blockIdx.x;
    const int j = threadIdx.x;
    __shared__ float hs[HIDDEN];
    if (j < HIDDEN) {
        const float* pr = &g_pooled[b * CIN];
        const float* wr = &w1[j * CIN];
        float s = 0.f;
#pragma unroll 4
        for (int c = 0; c < CIN; c++) s += pr[c] * wr[c];
        hs[j] = fmaxf(s, 0.f);
    }
    __syncthreads();
    if (j == 0) {
        float lg[KBANK];
#pragma unroll
        for (int k = 0; k < KBANK; k++) {
            float s = b2[k];
            for (int h = 0; h < HIDDEN; h++) s += hs[h] * w2[k * HIDDEN + h];
            lg[k] = s * (1.0f / TEMP);
        }
        float m = lg[0];
#pragma unroll
        for (int k = 1; k < KBANK; k++) m = fmaxf(m, lg[k]);
        float e[KBANK], Z = 0.f;
#pragma unroll
        for (int k = 0; k < KBANK; k++) { e[k] = expf(lg[k] - m); Z += e[k]; }
        float inv = 1.0f / Z;
#pragma unroll
        for (int k = 0; k < KBANK; k++) g_att[b * KBANK + k] = e[k] * inv;
    }
}

// ---------------- Kernel 3: weight aggregation -> [b][rs][oc][ci], tf32-rounded ---
__global__ void agg_kernel(const float* __restrict__ bank) {
    const int oc = blockIdx.x;
    const int b  = blockIdx.y;
    const float a0 = g_att[b * 4 + 0], a1 = g_att[b * 4 + 1];
    const float a2 = g_att[b * 4 + 2], a3 = g_att[b * 4 + 3];
    const float* w = bank + (size_t)oc * BANK_O_STRIDE;
    uint32_t* dst = (uint32_t*)g_aggw + (size_t)b * 9 * 65536 + oc * 256;
    for (int t = threadIdx.x; t < 2304; t += 256) {
        float v = a0 * w[t] + a1 * w[t + BANK_K_STRIDE]
                + a2 * w[t + 2 * BANK_K_STRIDE] + a3 * w[t + 3 * BANK_K_STRIDE];
        int ci = t / 9;
        int rs = t - 9 * ci;
        dst[rs * 65536 + ci] = f2tf32(v);
    }
}

// ---------------- Kernel 4: tf32 mma.sync conv, cp.async, 2 CTAs/SM ---------------
__global__ __launch_bounds__(256, 2)
void conv_mma(float* __restrict__ out) {
    extern __shared__ char smem[];
    uint32_t* A_u = (uint32_t*)smem;                     // 2 x [128][ASTR]
    uint32_t* xr  = (uint32_t*)(smem + SM_XR_OFF);       // 2 x [32 ci][4 rows][XRROW]
    const uint32_t A_sb  = smem_u32(smem);
    const uint32_t XR_sb = A_sb + SM_XR_OFF;

    const int tid  = threadIdx.x;
    const int wid  = tid >> 5;
    const int lane = tid & 31;
    const int g    = lane >> 2;
    const int t    = lane & 3;
    const int wm   = wid & 1;        // warp M tile (64 oc)
    const int wn   = wid >> 1;       // warp N tile (32 px): row = wn>>1, col0 = (wn&1)*32

    const int b   = blockIdx.z;
    const int oc0 = blockIdx.y << 7;
    const int y0  = blockIdx.x << 1; // 2 output rows per CTA

    const uint32_t* xtb = g_xtf + (size_t)b * (CIN * HW * HW);
    const float*    wb  = g_aggw + (size_t)b * 9 * 65536;

    float acc[4][4][4];
#pragma unroll
    for (int mf = 0; mf < 4; mf++)
#pragma unroll
        for (int nf = 0; nf < 4; nf++)
#pragma unroll
            for (int k = 0; k < 4; k++) acc[mf][nf][k] = 0.f;

    // per-thread A staging slots
    const int am0 = tid >> 3;            // oc row for i=0; +32 per i
    const int akq = (tid & 7) << 2;      // ci quad

    // prologue: zero halo columns of both xr buffers (never rewritten)
    {
        int buf = tid >= 128;
        int rem = tid & 127;
        int ci = rem >> 2, ri = rem & 3;
        uint32_t* d = xr + buf * XR_HALF + ci * XRCI + ri * XRROW;
        d[3] = 0u; d[68] = 0u;
    }

    // issue stage-0 A and chunk-0 xr
    {
        const float* arow = wb + oc0 * 256;   // rs=0, ci0=0
#pragma unroll
        for (int i = 0; i < 4; i++) {
            int m = am0 + i * 32;
            cp_async16(A_sb + (m * ASTR + akq) * 4, arow + m * 256 + akq, 16);
        }
#pragma unroll
        for (int i = 0; i < 8; i++) {
            int q = tid + i * 256;
            int ci = q >> 6, rem = q & 63;
            int ri = rem >> 4, c4 = (rem & 15) << 2;
            int xrow = y0 - 1 + ri;
            uint32_t ok = ((unsigned)xrow < (unsigned)HW) ? 16u : 0u;
            cp_async16(XR_sb + (ci * XRCI + ri * XRROW + 4 + c4) * 4,
                       xtb + ci * (HW * HW) + xrow * HW + c4, ok);
        }
        CP_COMMIT();
    }

    // compute-invariant bases
    const uint32_t* a_tb = A_u + (wm * 64 + g) * ASTR + t;
    const uint32_t* x_tb = xr + t * XRCI + (wn >> 1) * XRROW + 3 + (wn & 1) * 32 + g;

    int chunk = 0, rs = 0;
    for (int s = 0; s < 72; s++) {
        CP_WAIT0();
        __syncthreads();

        // ---- prefetch next stage (overlaps with this stage's MMAs) ----
        int rs_n = rs + 1, chunk_n = chunk;
        if (rs_n == 9) { rs_n = 0; chunk_n++; }
        if (s + 1 < 72) {
            const float* arow = wb + (size_t)rs_n * 65536 + oc0 * 256 + chunk_n * 32;
            uint32_t Ad = A_sb + ((s + 1) & 1) * (A_HALF * 4);
#pragma unroll
            for (int i = 0; i < 4; i++) {
                int m = am0 + i * 32;
                cp_async16(Ad + (m * ASTR + akq) * 4, arow + m * 256 + akq, 16);
            }
        }
        if (rs == 0 && chunk + 1 < 8) {
            const uint32_t* xcb = xtb + (chunk + 1) * 32 * (HW * HW);
            uint32_t Xd = XR_sb + ((chunk + 1) & 1) * (XR_HALF * 4);
#pragma unroll
            for (int i = 0; i < 8; i++) {
                int q = tid + i * 256;
                int ci = q >> 6, rem = q & 63;
                int ri = rem >> 4, c4 = (rem & 15) << 2;
                int xrow = y0 - 1 + ri;
                uint32_t ok = ((unsigned)xrow < (unsigned)HW) ? 16u : 0u;
                cp_async16(Xd + (ci * XRCI + ri * XRROW + 4 + c4) * 4,
                           xcb + ci * (HW * HW) + xrow * HW + c4, ok);
            }
        }
        CP_COMMIT();

        // ---- compute stage s ----
        const int r = rs / 3, sc = rs - 3 * r;
        const uint32_t* a_base = a_tb + (s & 1) * A_HALF;
        const uint32_t* xs_ = x_tb + (chunk & 1) * XR_HALF + r * XRROW + sc;
#pragma unroll
        for (int ks = 0; ks < 4; ks++) {
            const uint32_t* ap = a_base + ks * 8;
            uint32_t af[4][4];
#pragma unroll
            for (int mf = 0; mf < 4; mf++) {
                const uint32_t* am = ap + mf * 16 * ASTR;
                af[mf][0] = am[0];
                af[mf][1] = am[8 * ASTR];
                af[mf][2] = am[4];
                af[mf][3] = am[8 * ASTR + 4];
            }
            const uint32_t* xp = xs_ + ks * 8 * XRCI;
            uint32_t bf[4][2];
#pragma unroll
            for (int nf = 0; nf < 4; nf++) {
                bf[nf][0] = xp[nf * 8];
                bf[nf][1] = xp[nf * 8 + 4 * XRCI];
            }
#pragma unroll
            for (int mf = 0; mf < 4; mf++)
#pragma unroll
                for (int nf = 0; nf < 4; nf++)
                    mma_tf32(acc[mf][nf], af[mf], bf[nf]);
        }

        if (++rs == 9) { rs = 0; chunk++; }
    }

    // ---- epilogue ----
    const int ocr = oc0 + wm * 64 + g;
    const int ybase = (y0 + (wn >> 1)) * 64 + (wn & 1) * 32;
#pragma unroll
    for (int mf = 0; mf < 4; mf++) {
        float* o0 = out + ((size_t)(b * COUT + ocr + mf * 16)) * (HW * HW) + ybase;
        float* o1 = o0 + 8 * (HW * HW);
#pragma unroll
        for (int nf = 0; nf < 4; nf++) {
            int px0 = nf * 8 + 2 * t;
            *(float2*)(o0 + px0) = make_float2(acc[mf][nf][0], acc[mf][nf][1]);
            *(float2*)(o1 + px0) = make_float2(acc[mf][nf][2], acc[mf][nf][3]);
        }
    }
}

// ---------------- launch ----------------
extern "C" void kernel_launch(void* const* d_in, const int* in_sizes, int n_in,
                              void* d_out, int out_size) {
    (void)in_sizes; (void)n_in; (void)out_size;
    const float* x    = (const float*)d_in[0];  // [16,256,64,64]
    const float* bank = (const float*)d_in[1];  // [4,256,256,3,3]
    const float* w1   = (const float*)d_in[2];  // [65,256]
    const float* w2   = (const float*)d_in[3];  // [4,65]
    const float* b2   = (const float*)d_in[4];  // [4]
    float* out = (float*)d_out;                 // [16,256,64,64]

    static bool attr_set = false;
    if (!attr_set) {
        cudaFuncSetAttribute(conv_mma, cudaFuncAttributeMaxDynamicSharedMemorySize, SM_TOTAL);
        attr_set = true;
    }

    pool_kernel<<<BATCH * CIN, 256>>>(x);
    att_kernel<<<BATCH, 128>>>(w1, w2, b2);
    agg_kernel<<<dim3(COUT, BATCH), 256>>>(bank);
    conv_mma<<<dim3(32, 2, BATCH), 256, SM_TOTAL>>>(out);
}

// round 15
// speedup vs baseline: 1.4292x; 1.0006x over previous
#include <cuda_runtime.h>
#include <cstdint>
#include <cstddef>

// ---------------- problem constants ----------------
#define BATCH   16
#define CIN     256
#define COUT    256
#define HW      64
#define KBANK   4
#define HIDDEN  65
#define TEMP    34.0f
#define BANK_K_STRIDE (256*256*9)
#define BANK_O_STRIDE (256*9)

// ---------------- conv tiling ----------------
// CTA: 128 oc x 128 px (2 output rows), 8 warps = 2(M) x 4(N), warp tile 64x32.
// 2 CTAs / SM. K = 2304 as 8 ci-chunks of 32 x 9 shifts = 72 cp.async stages.
#define ASTR    36               // A smem row stride (floats); 36 % 32 == 4 -> conflict-free frags
#define A_HALF  (128 * ASTR)     // floats per A buffer (4608)
#define XRROW   72               // x-row cache row stride; col c at 4+c, halos at 3 & 68
#define XRCI    296              // ci stride (4 rows*72=288 +8 pad); 296 % 32 == 8 -> conflict-free
#define XR_HALF (32 * XRCI)      // floats per xr buffer (9472)
#define SM_XR_OFF  (2 * A_HALF * 4)                 // 36864
#define SM_TOTAL   (SM_XR_OFF + 2 * XR_HALF * 4)    // 36864 + 75776 = 112640 (2 CTAs/SM)

// ---------------- scratch (allocation-free) ----------------
__device__ float    g_pooled[BATCH * CIN];
__device__ float    g_att[BATCH * KBANK];
__device__ float    g_aggw[BATCH * 9 * COUT * CIN];      // [b][rs][oc][ci], tf32-rounded
__device__ uint32_t g_xtf[BATCH * CIN * HW * HW];        // x, tf32-rounded bits

// ---------------- helpers ----------------
__device__ __forceinline__ uint32_t f2tf32(float f) {
    uint32_t u;
    asm("cvt.rna.tf32.f32 %0, %1;" : "=r"(u) : "f"(f));
    return u;
}
__device__ __forceinline__ uint32_t smem_u32(const void* p) {
    uint32_t a;
    asm("{ .reg .u64 t; cvta.to.shared.u64 t, %1; cvt.u32.u64 %0, t; }" : "=r"(a) : "l"(p));
    return a;
}
__device__ __forceinline__ void cp_async16(uint32_t dst, const void* src, uint32_t srcsize) {
    asm volatile("cp.async.cg.shared.global [%0], [%1], 16, %2;"
                 :: "r"(dst), "l"(src), "r"(srcsize) : "memory");
}
#define CP_COMMIT() asm volatile("cp.async.commit_group;" ::: "memory")
#define CP_WAIT0()  asm volatile("cp.async.wait_group 0;" ::: "memory")

__device__ __forceinline__ void mma_tf32(float* d, const uint32_t* a, const uint32_t* b) {
    asm volatile(
        "mma.sync.aligned.m16n8k8.row.col.f32.tf32.tf32.f32 "
        "{%0,%1,%2,%3}, {%4,%5,%6,%7}, {%8,%9}, {%0,%1,%2,%3};"
        : "+f"(d[0]), "+f"(d[1]), "+f"(d[2]), "+f"(d[3])
        : "r"(a[0]), "r"(a[1]), "r"(a[2]), "r"(a[3]), "r"(b[0]), "r"(b[1]));
}

// ---------------- Kernel 1: global average pool + x tf32 pre-round ----------------
__global__ void pool_kernel(const float* __restrict__ x) {
    const int bc = blockIdx.x;
    const float4* p = (const float4*)(x + (size_t)bc * (HW * HW));
    uint4* q = (uint4*)(g_xtf + (size_t)bc * (HW * HW));
    float s = 0.f;
#pragma unroll 4
    for (int i = threadIdx.x; i < 1024; i += 256) {
        float4 v = p[i];
        s += (v.x + v.y) + (v.z + v.w);
        q[i] = make_uint4(f2tf32(v.x), f2tf32(v.y), f2tf32(v.z), f2tf32(v.w));
    }
#pragma unroll
    for (int o = 16; o > 0; o >>= 1) s += __shfl_xor_sync(0xFFFFFFFFu, s, o);
    __shared__ float red[8];
    if ((threadIdx.x & 31) == 0) red[threadIdx.x >> 5] = s;
    __syncthreads();
    if (threadIdx.x == 0) {
        float t = 0.f;
#pragma unroll
        for (int w = 0; w < 8; w++) t += red[w];
        g_pooled[bc] = t * (1.0f / (HW * HW));
    }
}

// ---------------- Kernel 2: attention MLP + softmax ----------------
__global__ void att_kernel(const float* __restrict__ w1,
                           const float* __restrict__ w2,
                           const float* __restrict__ b2) {
    const int b = blockIdx.x;
    const int j = threadIdx.x;
    __shared__ float hs[HIDDEN];
    if (j < HIDDEN) {
        const float* pr = &g_pooled[b * CIN];
        const float* wr = &w1[j * CIN];
        float s = 0.f;
#pragma unroll 4
        for (int c = 0; c < CIN; c++) s += pr[c] * wr[c];
        hs[j] = fmaxf(s, 0.f);
    }
    __syncthreads();
    if (j == 0) {
        float lg[KBANK];
#pragma unroll
        for (int k = 0; k < KBANK; k++) {
            float s = b2[k];
            for (int h = 0; h < HIDDEN; h++) s += hs[h] * w2[k * HIDDEN + h];
            lg[k] = s * (1.0f / TEMP);
        }
        float m = lg[0];
#pragma unroll
        for (int k = 1; k < KBANK; k++) m = fmaxf(m, lg[k]);
        float e[KBANK], Z = 0.f;
#pragma unroll
        for (int k = 0; k < KBANK; k++) { e[k] = expf(lg[k] - m); Z += e[k]; }
        float inv = 1.0f / Z;
#pragma unroll
        for (int k = 0; k < KBANK; k++) g_att[b * KBANK + k] = e[k] * inv;
    }
}

// ---------------- Kernel 3: weight aggregation -> [b][rs][oc][ci], tf32-rounded ---
__global__ void agg_kernel(const float* __restrict__ bank) {
    const int oc = blockIdx.x;
    const int b  = blockIdx.y;
    const float a0 = g_att[b * 4 + 0], a1 = g_att[b * 4 + 1];
    const float a2 = g_att[b * 4 + 2], a3 = g_att[b * 4 + 3];
    const float* w = bank + (size_t)oc * BANK_O_STRIDE;
    uint32_t* dst = (uint32_t*)g_aggw + (size_t)b * 9 * 65536 + oc * 256;
    for (int t = threadIdx.x; t < 2304; t += 256) {
        float v = a0 * w[t] + a1 * w[t + BANK_K_STRIDE]
                + a2 * w[t + 2 * BANK_K_STRIDE] + a3 * w[t + 3 * BANK_K_STRIDE];
        int ci = t / 9;
        int rs = t - 9 * ci;
        dst[rs * 65536 + ci] = f2tf32(v);
    }
}

// ---------------- Kernel 4: tf32 mma.sync conv, cp.async, 2 CTAs/SM ---------------
__global__ __launch_bounds__(256, 2)
void conv_mma(float* __restrict__ out) {
    extern __shared__ char smem[];
    uint32_t* A_u = (uint32_t*)smem;                     // 2 x [128][ASTR]
    uint32_t* xr  = (uint32_t*)(smem + SM_XR_OFF);       // 2 x [32 ci][4 rows][XRROW]
    const uint32_t A_sb  = smem_u32(smem);
    const uint32_t XR_sb = A_sb + SM_XR_OFF;

    const int tid  = threadIdx.x;
    const int wid  = tid >> 5;
    const int lane = tid & 31;
    const int g    = lane >> 2;
    const int t    = lane & 3;
    const int wm   = wid & 1;        // warp M tile (64 oc)
    const int wn   = wid >> 1;       // warp N tile (32 px): row = wn>>1, col0 = (wn&1)*32

    const int b   = blockIdx.z;
    const int oc0 = blockIdx.y << 7;
    const int y0  = blockIdx.x << 1; // 2 output rows per CTA

    const uint32_t* xtb = g_xtf + (size_t)b * (CIN * HW * HW);
    const float*    wb  = g_aggw + (size_t)b * 9 * 65536;

    float acc[4][4][4];
#pragma unroll
    for (int mf = 0; mf < 4; mf++)
#pragma unroll
        for (int nf = 0; nf < 4; nf++)
#pragma unroll
            for (int k = 0; k < 4; k++) acc[mf][nf][k] = 0.f;

    // per-thread A staging slots
    const int am0 = tid >> 3;            // oc row for i=0; +32 per i
    const int akq = (tid & 7) << 2;      // ci quad

    // prologue: zero halo columns of both xr buffers (never rewritten)
    {
        int buf = tid >= 128;
        int rem = tid & 127;
        int ci = rem >> 2, ri = rem & 3;
        uint32_t* d = xr + buf * XR_HALF + ci * XRCI + ri * XRROW;
        d[3] = 0u; d[68] = 0u;
    }

    // issue stage-0 A and chunk-0 xr
    {
        const float* arow = wb + oc0 * 256;   // rs=0, ci0=0
#pragma unroll
        for (int i = 0; i < 4; i++) {
            int m = am0 + i * 32;
            cp_async16(A_sb + (m * ASTR + akq) * 4, arow + m * 256 + akq, 16);
        }
#pragma unroll
        for (int i = 0; i < 8; i++) {
            int q = tid + i * 256;
            int ci = q >> 6, rem = q & 63;
            int ri = rem >> 4, c4 = (rem & 15) << 2;
            int xrow = y0 - 1 + ri;
            uint32_t ok = ((unsigned)xrow < (unsigned)HW) ? 16u : 0u;
            cp_async16(XR_sb + (ci * XRCI + ri * XRROW + 4 + c4) * 4,
                       xtb + ci * (HW * HW) + xrow * HW + c4, ok);
        }
        CP_COMMIT();
    }

    // compute-invariant bases
    const uint32_t* a_tb = A_u + (wm * 64 + g) * ASTR + t;
    const uint32_t* x_tb = xr + t * XRCI + (wn >> 1) * XRROW + 3 + (wn & 1) * 32 + g;

    int chunk = 0, rs = 0;
    for (int s = 0; s < 72; s++) {
        CP_WAIT0();
        __syncthreads();

        // ---- prefetch next stage (overlaps with this stage's MMAs) ----
        int rs_n = rs + 1, chunk_n = chunk;
        if (rs_n == 9) { rs_n = 0; chunk_n++; }
        if (s + 1 < 72) {
            const float* arow = wb + (size_t)rs_n * 65536 + oc0 * 256 + chunk_n * 32;
            uint32_t Ad = A_sb + ((s + 1) & 1) * (A_HALF * 4);
#pragma unroll
            for (int i = 0; i < 4; i++) {
                int m = am0 + i * 32;
                cp_async16(Ad + (m * ASTR + akq) * 4, arow + m * 256 + akq, 16);
            }
        }
        if (rs == 0 && chunk + 1 < 8) {
            const uint32_t* xcb = xtb + (chunk + 1) * 32 * (HW * HW);
            uint32_t Xd = XR_sb + ((chunk + 1) & 1) * (XR_HALF * 4);
#pragma unroll
            for (int i = 0; i < 8; i++) {
                int q = tid + i * 256;
                int ci = q >> 6, rem = q & 63;
                int ri = rem >> 4, c4 = (rem & 15) << 2;
                int xrow = y0 - 1 + ri;
                uint32_t ok = ((unsigned)xrow < (unsigned)HW) ? 16u : 0u;
                cp_async16(Xd + (ci * XRCI + ri * XRROW + 4 + c4) * 4,
                           xcb + ci * (HW * HW) + xrow * HW + c4, ok);
            }
        }
        CP_COMMIT();

        // ---- compute stage s ----
        const int r = rs / 3, sc = rs - 3 * r;
        const uint32_t* a_base = a_tb + (s & 1) * A_HALF;
        const uint32_t* xs_ = x_tb + (chunk & 1) * XR_HALF + r * XRROW + sc;
#pragma unroll
        for (int ks = 0; ks < 4; ks++) {
            const uint32_t* ap = a_base + ks * 8;
            uint32_t af[4][4];
#pragma unroll
            for (int mf = 0; mf < 4; mf++) {
                const uint32_t* am = ap + mf * 16 * ASTR;
                af[mf][0] = am[0];
                af[mf][1] = am[8 * ASTR];
                af[mf][2] = am[4];
                af[mf][3] = am[8 * ASTR + 4];
            }
            const uint32_t* xp = xs_ + ks * 8 * XRCI;
            uint32_t bf[4][2];
#pragma unroll
            for (int nf = 0; nf < 4; nf++) {
                bf[nf][0] = xp[nf * 8];
                bf[nf][1] = xp[nf * 8 + 4 * XRCI];
            }
#pragma unroll
            for (int mf = 0; mf < 4; mf++)
#pragma unroll
                for (int nf = 0; nf < 4; nf++)
                    mma_tf32(acc[mf][nf], af[mf], bf[nf]);
        }

        if (++rs == 9) { rs = 0; chunk++; }
    }

    // ---- epilogue ----
    const int ocr = oc0 + wm * 64 + g;
    const int ybase = (y0 + (wn >> 1)) * 64 + (wn & 1) * 32;
#pragma unroll
    for (int mf = 0; mf < 4; mf++) {
        float* o0 = out + ((size_t)(b * COUT + ocr + mf * 16)) * (HW * HW) + ybase;
        float* o1 = o0 + 8 * (HW * HW);
#pragma unroll
        for (int nf = 0; nf < 4; nf++) {
            int px0 = nf * 8 + 2 * t;
            *(float2*)(o0 + px0) = make_float2(acc[mf][nf][0], acc[mf][nf][1]);
            *(float2*)(o1 + px0) = make_float2(acc[mf][nf][2], acc[mf][nf][3]);
        }
    }
}

// ---------------- launch ----------------
extern "C" void kernel_launch(void* const* d_in, const int* in_sizes, int n_in,
                              void* d_out, int out_size) {
    (void)in_sizes; (void)n_in; (void)out_size;
    const float* x    = (const float*)d_in[0];  // [16,256,64,64]
    const float* bank = (const float*)d_in[1];  // [4,256,256,3,3]
    const float* w1   = (const float*)d_in[2];  // [65,256]
    const float* w2   = (const float*)d_in[3];  // [4,65]
    const float* b2   = (const float*)d_in[4];  // [4]
    float* out = (float*)d_out;                 // [16,256,64,64]

    static bool attr_set = false;
    if (!attr_set) {
        cudaFuncSetAttribute(conv_mma, cudaFuncAttributeMaxDynamicSharedMemorySize, SM_TOTAL);
        attr_set = true;
    }

    pool_kernel<<<BATCH * CIN, 256>>>(x);
    att_kernel<<<BATCH, 128>>>(w1, w2, b2);
    agg_kernel<<<dim3(COUT, BATCH), 256>>>(bank);
    conv_mma<<<dim3(32, 2, BATCH), 256, SM_TOTAL>>>(out);
}

// round 17
// speedup vs baseline: 2.2266x; 1.5579x over previous
#include <cuda_runtime.h>
#include <cuda_fp16.h>
#include <cstdint>
#include <cstddef>

// ---------------- problem constants ----------------
#define BATCH   16
#define CIN     256
#define COUT    256
#define HW      64
#define KBANK   4
#define HIDDEN  65
#define TEMP    34.0f
#define BANK_K_STRIDE (256*256*9)
#define BANK_O_STRIDE (256*9)

// ---------------- conv tiling ----------------
// CTA: 128 oc x 128 px (2 output rows), 8 warps = 2(M) x 4(N), warp tile 64x32.
// fp16 m16n8k16: 32 ci per stage = 2 k-steps. 72 cp.async stages. 2 CTAs/SM.
#define ASTR_W   20              // A row stride in 32-bit words (16 data + 4 pad); g*20 mod 32 distinct
#define A_HALF_W (128 * ASTR_W)  // 2560 words per A buffer (10240 B)
#define XRROW2   72              // xr row stride in words; px p at word 4+p, halos at 3 & 68
#define XRCI2    296             // ci2 stride in words (4*72 + 8); 296 % 32 == 8 -> conflict-free
#define XR_HALF_W (16 * XRCI2)   // 4736 words per xr buffer (18944 B)
#define SM_XR_OFF  (2 * A_HALF_W * 4)                  // 20480
#define SM_TOTAL   (SM_XR_OFF + 2 * XR_HALF_W * 4)     // 20480 + 37888 = 58368

// ---------------- scratch (allocation-free) ----------------
__device__ float   g_pooled[BATCH * CIN];
__device__ float   g_att[BATCH * KBANK];
__device__ __half  g_aggh[BATCH * 9 * COUT * CIN];     // [b][rs][oc][ci] fp16 weights
__device__ __half2 g_xh2[BATCH * 128 * HW * HW];       // [b][ci2][px]: (ci even, ci odd)

// ---------------- helpers ----------------
__device__ __forceinline__ uint32_t h2_bits(__half2 h) {
    union { __half2 h; uint32_t u; } c;
    c.h = h;
    return c.u;
}
__device__ __forceinline__ uint32_t smem_u32(const void* p) {
    uint32_t a;
    asm("{ .reg .u64 t; cvta.to.shared.u64 t, %1; cvt.u32.u64 %0, t; }" : "=r"(a) : "l"(p));
    return a;
}
__device__ __forceinline__ void cp_async16(uint32_t dst, const void* src, uint32_t srcsize) {
    asm volatile("cp.async.cg.shared.global [%0], [%1], 16, %2;"
                 :: "r"(dst), "l"(src), "r"(srcsize) : "memory");
}
#define CP_COMMIT() asm volatile("cp.async.commit_group;" ::: "memory")
#define CP_WAIT0()  asm volatile("cp.async.wait_group 0;" ::: "memory")

__device__ __forceinline__ void mma_f16(float* d, const uint32_t* a, const uint32_t* b) {
    asm volatile(
        "mma.sync.aligned.m16n8k16.row.col.f32.f16.f16.f32 "
        "{%0,%1,%2,%3}, {%4,%5,%6,%7}, {%8,%9}, {%0,%1,%2,%3};"
        : "+f"(d[0]), "+f"(d[1]), "+f"(d[2]), "+f"(d[3])
        : "r"(a[0]), "r"(a[1]), "r"(a[2]), "r"(a[3]), "r"(b[0]), "r"(b[1]));
}

// ---------------- Kernel 1: pool + pack x into channel-pair half2 planes --------
__global__ void pool_kernel(const float* __restrict__ x) {
    const int bp = blockIdx.x;             // b*128 + c2
    const int b  = bp >> 7, c2 = bp & 127;
    const float4* p0 = (const float4*)(x + ((size_t)b * 256 + 2 * c2) * (HW * HW));
    const float4* p1 = p0 + (HW * HW / 4);
    uint4* q = (uint4*)(g_xh2 + ((size_t)b * 128 + c2) * (HW * HW));
    float s0 = 0.f, s1 = 0.f;
#pragma unroll 2
    for (int i = threadIdx.x; i < 1024; i += 256) {
        float4 v0 = p0[i], v1 = p1[i];
        s0 += (v0.x + v0.y) + (v0.z + v0.w);
        s1 += (v1.x + v1.y) + (v1.z + v1.w);
        uint4 u;
        u.x = h2_bits(__floats2half2_rn(v0.x, v1.x));
        u.y = h2_bits(__floats2half2_rn(v0.y, v1.y));
        u.z = h2_bits(__floats2half2_rn(v0.z, v1.z));
        u.w = h2_bits(__floats2half2_rn(v0.w, v1.w));
        q[i] = u;
    }
#pragma unroll
    for (int o = 16; o > 0; o >>= 1) {
        s0 += __shfl_xor_sync(0xFFFFFFFFu, s0, o);
        s1 += __shfl_xor_sync(0xFFFFFFFFu, s1, o);
    }
    __shared__ float red[16];
    if ((threadIdx.x & 31) == 0) {
        red[(threadIdx.x >> 5) * 2]     = s0;
        red[(threadIdx.x >> 5) * 2 + 1] = s1;
    }
    __syncthreads();
    if (threadIdx.x == 0) {
        float t0 = 0.f, t1 = 0.f;
#pragma unroll
        for (int w = 0; w < 8; w++) { t0 += red[2 * w]; t1 += red[2 * w + 1]; }
        g_pooled[b * 256 + 2 * c2]     = t0 * (1.0f / (HW * HW));
        g_pooled[b * 256 + 2 * c2 + 1] = t1 * (1.0f / (HW * HW));
    }
}

// ---------------- Kernel 2: attention MLP + softmax ----------------
__global__ void att_kernel(const float* __restrict__ w1,
                           const float* __restrict__ w2,
                           const float* __restrict__ b2) {
    const int b = blockIdx.x;
    const int j = threadIdx.x;
    __shared__ float hs[HIDDEN];
    if (j < HIDDEN) {
        const float* pr = &g_pooled[b * CIN];
        const float* wr = &w1[j * CIN];
        float s = 0.f;
#pragma unroll 4
        for (int c = 0; c < CIN; c++) s += pr[c] * wr[c];
        hs[j] = fmaxf(s, 0.f);
    }
    __syncthreads();
    if (j == 0) {
        float lg[KBANK];
#pragma unroll
        for (int k = 0; k < KBANK; k++) {
            float s = b2[k];
            for (int h = 0; h < HIDDEN; h++) s += hs[h] * w2[k * HIDDEN + h];
            lg[k] = s * (1.0f / TEMP);
        }
        float m = lg[0];
#pragma unroll
        for (int k = 1; k < KBANK; k++) m = fmaxf(m, lg[k]);
        float e[KBANK], Z = 0.f;
#pragma unroll
        for (int k = 0; k < KBANK; k++) { e[k] = expf(lg[k] - m); Z += e[k]; }
        float inv = 1.0f / Z;
#pragma unroll
        for (int k = 0; k < KBANK; k++) g_att[b * KBANK + k] = e[k] * inv;
    }
}

// ---------------- Kernel 3: weight aggregation -> [b][rs][oc][ci] fp16 -----------
__global__ void agg_kernel(const float* __restrict__ bank) {
    const int oc = blockIdx.x;
    const int b  = blockIdx.y;
    const float a0 = g_att[b * 4 + 0], a1 = g_att[b * 4 + 1];
    const float a2 = g_att[b * 4 + 2], a3 = g_att[b * 4 + 3];
    const float* w = bank + (size_t)oc * BANK_O_STRIDE;
    __half* dst = g_aggh + (size_t)b * 9 * 65536 + oc * 256;
    for (int t = threadIdx.x; t < 2304; t += 256) {
        float v = a0 * w[t] + a1 * w[t + BANK_K_STRIDE]
                + a2 * w[t + 2 * BANK_K_STRIDE] + a3 * w[t + 3 * BANK_K_STRIDE];
        int ci = t / 9;
        int rs = t - 9 * ci;
        dst[rs * 65536 + ci] = __float2half_rn(v);
    }
}

// ---------------- Kernel 4: fp16 m16n8k16 conv, cp.async, 2 CTAs/SM --------------
__global__ __launch_bounds__(256, 2)
void conv_mma(float* __restrict__ out) {
    extern __shared__ char smem[];
    uint32_t* A_u = (uint32_t*)smem;                     // 2 x [128][ASTR_W] half2 words
    uint32_t* xr  = (uint32_t*)(smem + SM_XR_OFF);       // 2 x [16 ci2][4 rows][XRROW2]
    const uint32_t A_sb  = smem_u32(smem);
    const uint32_t XR_sb = A_sb + SM_XR_OFF;

    const int tid  = threadIdx.x;
    const int wid  = tid >> 5;
    const int lane = tid & 31;
    const int g    = lane >> 2;
    const int t    = lane & 3;
    const int wm   = wid & 1;        // warp M tile (64 oc)
    const int wn   = wid >> 1;       // warp N tile: row = wn>>1, col0 = (wn&1)*32

    const int b   = blockIdx.z;
    const int oc0 = blockIdx.y << 7;
    const int y0  = blockIdx.x << 1; // 2 output rows per CTA

    const __half2* xtb = g_xh2 + (size_t)b * 128 * (HW * HW);
    const __half*  wb  = g_aggh + (size_t)b * 9 * 65536;

    float acc[4][4][4];
#pragma unroll
    for (int mf = 0; mf < 4; mf++)
#pragma unroll
        for (int nf = 0; nf < 4; nf++)
#pragma unroll
            for (int k = 0; k < 4; k++) acc[mf][nf][k] = 0.f;

    // prologue: zero halo words (3 and 68) of both xr buffers (never rewritten)
    if (tid < 128) {
        int buf = tid >> 6, rem = tid & 63;
        int ci2 = rem >> 2, ri = rem & 3;
        uint32_t* d = xr + buf * XR_HALF_W + ci2 * XRCI2 + ri * XRROW2;
        d[3] = 0u; d[68] = 0u;
    }

    // issue stage-0 A and chunk-0 xr
    {
        const __half* arow = wb + oc0 * 256;   // rs=0, ci0=0
#pragma unroll
        for (int j = 0; j < 2; j++) {          // 512 A granules (16B = 8 halves)
            int gi = tid + j * 256;
            int m = gi >> 2, kq = gi & 3;
            cp_async16(A_sb + (m * ASTR_W + kq * 4) * 4, arow + m * 256 + kq * 8, 16);
        }
#pragma unroll
        for (int j = 0; j < 4; j++) {          // 1024 xr granules (16B = 4 half2 px)
            int gi = tid + j * 256;
            int ci2 = gi >> 6, rem = gi & 63;
            int ri = rem >> 4, c4 = (rem & 15) << 2;
            int xrow = y0 - 1 + ri;
            uint32_t ok = ((unsigned)xrow < (unsigned)HW) ? 16u : 0u;
            cp_async16(XR_sb + (ci2 * XRCI2 + ri * XRROW2 + 4 + c4) * 4,
                       xtb + ci2 * (HW * HW) + xrow * HW + c4, ok);
        }
        CP_COMMIT();
    }

    // compute-invariant bases
    const uint32_t* a_tb = A_u + (wm * 64 + g) * ASTR_W + t;
    const uint32_t* x_tb = xr + t * XRCI2 + (wn >> 1) * XRROW2 + 3 + (wn & 1) * 32 + g;

    int chunk = 0, rs = 0;
    for (int s = 0; s < 72; s++) {
        CP_WAIT0();
        __syncthreads();

        // ---- prefetch next stage ----
        int rs_n = rs + 1, chunk_n = chunk;
        if (rs_n == 9) { rs_n = 0; chunk_n++; }
        if (s + 1 < 72) {
            const __half* arow = wb + (size_t)rs_n * 65536 + oc0 * 256 + chunk_n * 32;
            uint32_t Ad = A_sb + ((s + 1) & 1) * (A_HALF_W * 4);
#pragma unroll
            for (int j = 0; j < 2; j++) {
                int gi = tid + j * 256;
                int m = gi >> 2, kq = gi & 3;
                cp_async16(Ad + (m * ASTR_W + kq * 4) * 4, arow + m * 256 + kq * 8, 16);
            }
        }
        if (rs == 0 && chunk + 1 < 8) {
            const __half2* xcb = xtb + (chunk + 1) * 16 * (HW * HW);
            uint32_t Xd = XR_sb + ((chunk + 1) & 1) * (XR_HALF_W * 4);
#pragma unroll
            for (int j = 0; j < 4; j++) {
                int gi = tid + j * 256;
                int ci2 = gi >> 6, rem = gi & 63;
                int ri = rem >> 4, c4 = (rem & 15) << 2;
                int xrow = y0 - 1 + ri;
                uint32_t ok = ((unsigned)xrow < (unsigned)HW) ? 16u : 0u;
                cp_async16(Xd + (ci2 * XRCI2 + ri * XRROW2 + 4 + c4) * 4,
                           xcb + ci2 * (HW * HW) + xrow * HW + c4, ok);
            }
        }
        CP_COMMIT();

        // ---- compute stage s: 2 k-steps of 16 ci ----
        const int r = rs / 3, sc = rs - 3 * r;
        const uint32_t* a_base = a_tb + (s & 1) * A_HALF_W;
        const uint32_t* xs_ = x_tb + (chunk & 1) * XR_HALF_W + r * XRROW2 + sc;
#pragma unroll
        for (int ks = 0; ks < 2; ks++) {
            const uint32_t* ap = a_base + ks * 8;
            uint32_t af[4][4];
#pragma unroll
            for (int mf = 0; mf < 4; mf++) {
                const uint32_t* am = ap + mf * 16 * ASTR_W;
                af[mf][0] = am[0];
                af[mf][1] = am[8 * ASTR_W];
                af[mf][2] = am[4];
                af[mf][3] = am[8 * ASTR_W + 4];
            }
            const uint32_t* xp = xs_ + ks * 8 * XRCI2;
            uint32_t bf[4][2];
#pragma unroll
            for (int nf = 0; nf < 4; nf++) {
                bf[nf][0] = xp[nf * 8];
                bf[nf][1] = xp[nf * 8 + 4 * XRCI2];
            }
#pragma unroll
            for (int mf = 0; mf < 4; mf++)
#pragma unroll
                for (int nf = 0; nf < 4; nf++)
                    mma_f16(acc[mf][nf], af[mf], bf[nf]);
        }

        if (++rs == 9) { rs = 0; chunk++; }
    }

    // ---- epilogue ----
    const int ocr = oc0 + wm * 64 + g;
    const int ybase = (y0 + (wn >> 1)) * 64 + (wn & 1) * 32;
#pragma unroll
    for (int mf = 0; mf < 4; mf++) {
        float* o0 = out + ((size_t)(b * COUT + ocr + mf * 16)) * (HW * HW) + ybase;
        float* o1 = o0 + 8 * (HW * HW);
#pragma unroll
        for (int nf = 0; nf < 4; nf++) {
            int px0 = nf * 8 + 2 * t;
            *(float2*)(o0 + px0) = make_float2(acc[mf][nf][0], acc[mf][nf][1]);
            *(float2*)(o1 + px0) = make_float2(acc[mf][nf][2], acc[mf][nf][3]);
        }
    }
}

// ---------------- launch ----------------
extern "C" void kernel_launch(void* const* d_in, const int* in_sizes, int n_in,
                              void* d_out, int out_size) {
    (void)in_sizes; (void)n_in; (void)out_size;
    const float* x    = (const float*)d_in[0];  // [16,256,64,64]
    const float* bank = (const float*)d_in[1];  // [4,256,256,3,3]
    const float* w1   = (const float*)d_in[2];  // [65,256]
    const float* w2   = (const float*)d_in[3];  // [4,65]
    const float* b2   = (const float*)d_in[4];  // [4]
    float* out = (float*)d_out;                 // [16,256,64,64]

    static bool attr_set = false;
    if (!attr_set) {
        cudaFuncSetAttribute(conv_mma, cudaFuncAttributeMaxDynamicSharedMemorySize, SM_TOTAL);
        attr_set = true;
    }

    pool_kernel<<<BATCH * 128, 256>>>(x);
    att_kernel<<<BATCH, 128>>>(w1, w2, b2);
    agg_kernel<<<dim3(COUT, BATCH), 256>>>(bank);
    conv_mma<<<dim3(32, 2, BATCH), 256, SM_TOTAL>>>(out);
}